// round 8
// baseline (speedup 1.0000x reference)
#include <cuda_runtime.h>
#include <cuda_bf16.h>

// VGAE encoder, pull-based, rank-1 norm factored out, agg/GEMM split:
//   norm_ij = dis_i*dis_j => A_hat h = dis (.) (t), t_i = u_i + sum_{j in N(i)} u_j,
//   u = dis (.) h. Layers store activations pre-scaled by dis (relu commutes, dis>0),
//   so CSR payload is src-only and gathers are weightless adds.
// Per layer: k_agg (warp-per-node gather -> t rows) + k_gemm (dense 256-row tiles,
// smem staged, thread-per-row). Heads share one agg + one dual GEMM.

#define N_MAX 131072
#define E_MAX 2097152   // >= E + 3*N (per-node padding to 4)

// Scratch (device globals; no allocations allowed)
__device__ int   g_is64;
__device__ int   g_alloc;            // CSR region allocator
__device__ int   g_cnt[N_MAX];       // in-degree (excluding self-loop)
__device__ int   g_rowstart[N_MAX];
__device__ int   g_cur[N_MAX];       // permutation cursor
__device__ float g_dis[N_MAX];       // deg^-1/2 (deg includes self-loop)
__device__ int   g_adjs[E_MAX];      // CSR payload: src only
__device__ float g_bufA[(size_t)N_MAX * 32];
__device__ float g_bufB[(size_t)N_MAX * 32];

// ---------------------------------------------------------------------------
// Init: zero g_cnt (all blocks); block 0 also detects edge dtype.
// int64 indices (< N ~ 1e5) have all-zero odd int32 words; int32 data never
// has 256 consecutive zero odd words.
// ---------------------------------------------------------------------------

__global__ __launch_bounds__(256) void k_init(const int* __restrict__ ei32,
                                              int E, int n) {
    int i = blockIdx.x * blockDim.x + threadIdx.x;
    if (i < n) g_cnt[i] = 0;
    if (blockIdx.x == 0) {
        int t = threadIdx.x;
        int n_check = 256 < E ? 256 : E;
        int nz = (t < n_check && ei32[2 * t + 1] != 0) ? 1 : 0;
        int any = __syncthreads_or(nz);
        if (t == 0) {
            g_is64 = !any;
            g_alloc = 0;
        }
    }
}

// Count in-degrees, 4 edges per thread (vectorized loads).
__global__ __launch_bounds__(256) void k_count(const void* __restrict__ eiv, int E) {
    int t = blockIdx.x * blockDim.x + threadIdx.x;
    int e0 = t * 4;
    if (e0 >= E) return;
    int d[4];
    int m = (E - e0 < 4) ? (E - e0) : 4;
    if (g_is64) {
        const long long* ei = (const long long*)eiv + (size_t)E + e0;
        if (m == 4) {
            longlong2 a = ((const longlong2*)ei)[0];
            longlong2 b = ((const longlong2*)ei)[1];
            d[0] = (int)a.x; d[1] = (int)a.y; d[2] = (int)b.x; d[3] = (int)b.y;
        } else {
            for (int k = 0; k < m; k++) d[k] = (int)ei[k];
        }
    } else {
        const int* ei = (const int*)eiv + (size_t)E + e0;
        if (m == 4) {
            int4 a = *(const int4*)ei;
            d[0] = a.x; d[1] = a.y; d[2] = a.z; d[3] = a.w;
        } else {
            for (int k = 0; k < m; k++) d[k] = ei[k];
        }
    }
    for (int k = 0; k < m; k++) atomicAdd(&g_cnt[d[k]], 1);
}

// Warp-per-node: CSR region alloc (padded to 4 for int4 loads) + u1 = dis (.) x.
__global__ __launch_bounds__(256) void k_rowalloc(const float* __restrict__ x,
                                                  float* __restrict__ u, int n) {
    int warp = (blockIdx.x * blockDim.x + threadIdx.x) >> 5;
    int lane = threadIdx.x & 31;
    if (warp >= n) return;
    int c = 0;
    if (lane == 0) {
        c = g_cnt[warp];
        int rs = atomicAdd(&g_alloc, (c + 3) & ~3);
        g_rowstart[warp] = rs;
        g_cur[warp] = rs;
    }
    c = __shfl_sync(0xFFFFFFFFu, c, 0);
    float dis = rsqrtf((float)(c + 1));  // +1 self-loop
    if (lane == 0) g_dis[warp] = dis;
    int idx = warp * 32 + lane;
    u[idx] = dis * x[idx];
}

// Permute edges into CSR, 4 edges per thread (4 atomics in flight).
__global__ __launch_bounds__(256) void k_permute(const void* __restrict__ eiv, int E) {
    int t = blockIdx.x * blockDim.x + threadIdx.x;
    int e0 = t * 4;
    if (e0 >= E) return;
    int s[4], d[4];
    int m = (E - e0 < 4) ? (E - e0) : 4;
    if (g_is64) {
        const long long* es = (const long long*)eiv + e0;
        const long long* ed = (const long long*)eiv + (size_t)E + e0;
        if (m == 4) {
            longlong2 a = ((const longlong2*)es)[0];
            longlong2 b = ((const longlong2*)es)[1];
            s[0] = (int)a.x; s[1] = (int)a.y; s[2] = (int)b.x; s[3] = (int)b.y;
            longlong2 c = ((const longlong2*)ed)[0];
            longlong2 e = ((const longlong2*)ed)[1];
            d[0] = (int)c.x; d[1] = (int)c.y; d[2] = (int)e.x; d[3] = (int)e.y;
        } else {
            for (int k = 0; k < m; k++) { s[k] = (int)es[k]; d[k] = (int)ed[k]; }
        }
    } else {
        const int* es = (const int*)eiv + e0;
        const int* ed = (const int*)eiv + (size_t)E + e0;
        if (m == 4) {
            int4 a = *(const int4*)es;
            s[0] = a.x; s[1] = a.y; s[2] = a.z; s[3] = a.w;
            int4 c = *(const int4*)ed;
            d[0] = c.x; d[1] = c.y; d[2] = c.z; d[3] = c.w;
        } else {
            for (int k = 0; k < m; k++) { s[k] = es[k]; d[k] = ed[k]; }
        }
    }
    int pos[4];
    for (int k = 0; k < m; k++) pos[k] = atomicAdd(&g_cur[d[k]], 1);
    for (int k = 0; k < m; k++) g_adjs[pos[k]] = s[k];
}

// ---------------------------------------------------------------------------
// Aggregation: warp = node; half-warps take alternating 4-edge int4 chunks;
// lane holds channels (2*sub, 2*sub+1) as float2.
//   t_i = r(u_i) + sum_j r(u_src_j),  r = relu if RELU.
// ---------------------------------------------------------------------------

__device__ __forceinline__ float2 relu2(float2 v) {
    v.x = fmaxf(v.x, 0.0f); v.y = fmaxf(v.y, 0.0f); return v;
}

template <int RELU>
__global__ __launch_bounds__(256) void k_agg(const float* __restrict__ u,
                                             float* __restrict__ t, int n)
{
    int warp = (blockIdx.x * blockDim.x + threadIdx.x) >> 5;
    int lane = threadIdx.x & 31;
    if (warp >= n) return;

    int half = lane >> 4;      // 0 or 1
    int sub  = lane & 15;      // channel pair index
    const float2* u2 = (const float2*)u;

    int rs  = g_rowstart[warp];
    int cnt = g_cnt[warp];

    // self term (half 0 only; halves summed later)
    float2 acc = make_float2(0.0f, 0.0f);
    if (half == 0) {
        float2 sv = u2[warp * 16 + sub];
        if (RELU) sv = relu2(sv);
        acc = sv;
    }

    int j = rs, end = rs + cnt;
    // 8 edges per iteration: each half-warp loads one int4 (4 src indices)
    for (; j + 8 <= end; j += 8) {
        int4 e = *(const int4*)(g_adjs + j + 4 * half);
        float2 v0 = u2[e.x * 16 + sub];
        float2 v1 = u2[e.y * 16 + sub];
        float2 v2 = u2[e.z * 16 + sub];
        float2 v3 = u2[e.w * 16 + sub];
        if (RELU) { v0 = relu2(v0); v1 = relu2(v1); v2 = relu2(v2); v3 = relu2(v3); }
        acc.x += (v0.x + v1.x) + (v2.x + v3.x);
        acc.y += (v0.y + v1.y) + (v2.y + v3.y);
    }
    for (; j + 2 <= end; j += 2) {
        float2 v = u2[g_adjs[j + half] * 16 + sub];
        if (RELU) v = relu2(v);
        acc.x += v.x; acc.y += v.y;
    }
    if (j < end && half == 0) {
        float2 v = u2[g_adjs[j] * 16 + sub];
        if (RELU) v = relu2(v);
        acc.x += v.x; acc.y += v.y;
    }

    // combine halves, half 0 writes the t row (coalesced 128B)
    acc.x += __shfl_xor_sync(0xFFFFFFFFu, acc.x, 16);
    acc.y += __shfl_xor_sync(0xFFFFFFFFu, acc.y, 16);
    if (half == 0) ((float2*)t)[warp * 16 + sub] = acc;
}

// ---------------------------------------------------------------------------
// Dense GEMM over t: 256 rows/block, smem-staged (pitch 33 floats: conflict-free),
// thread-per-row compute.  o = b + dis*(t@W); if PRE_OUT store dis*o.
// ---------------------------------------------------------------------------

__global__ __launch_bounds__(256) void k_gemm(
    const float* __restrict__ t, const float* __restrict__ W,
    const float* __restrict__ b, float* __restrict__ out, int n, int pre_out)
{
    __shared__ float sW[1024];       // W[k][j] at sW[k*32+j]
    __shared__ float st[256 * 33];   // staged rows, pitch 33
    int tid = threadIdx.x;
    ((float4*)sW)[tid] = ((const float4*)W)[tid];

    int base = blockIdx.x * 256;
    int rows = n - base; if (rows > 256) rows = 256;

    // stage in (coalesced)
    const float4* tin = (const float4*)(t + (size_t)base * 32);
    for (int i = tid; i < rows * 8; i += 256) {
        float4 v = tin[i];
        float* dst = &st[(i >> 3) * 33 + (i & 7) * 4];
        dst[0] = v.x; dst[1] = v.y; dst[2] = v.z; dst[3] = v.w;
    }
    __syncthreads();

    float xk[32];
    if (tid < rows) {
#pragma unroll
        for (int j = 0; j < 32; j++) xk[j] = st[tid * 33 + j];
    }
    __syncthreads();

    if (tid < rows) {
        float4 acc[8];
#pragma unroll
        for (int j = 0; j < 8; j++) acc[j] = make_float4(0.f, 0.f, 0.f, 0.f);
#pragma unroll
        for (int k = 0; k < 32; k++) {
            float a = xk[k];
#pragma unroll
            for (int j = 0; j < 8; j++) {
                float4 w = ((const float4*)sW)[k * 8 + j];
                acc[j].x += a * w.x; acc[j].y += a * w.y;
                acc[j].z += a * w.z; acc[j].w += a * w.w;
            }
        }
        float dis = g_dis[base + tid];
        float sb = pre_out ? dis : 1.0f;        // bias scale
        float ss = pre_out ? dis * dis : dis;   // sum scale
#pragma unroll
        for (int j = 0; j < 8; j++) {
            float4 bv = ((const float4*)b)[j];
            float* dst = &st[tid * 33 + j * 4];
            dst[0] = sb * bv.x + ss * acc[j].x;
            dst[1] = sb * bv.y + ss * acc[j].y;
            dst[2] = sb * bv.z + ss * acc[j].z;
            dst[3] = sb * bv.w + ss * acc[j].w;
        }
    }
    __syncthreads();

    // stage out (coalesced)
    float4* outp = (float4*)(out + (size_t)base * 32);
    for (int i = tid; i < rows * 8; i += 256) {
        const float* src = &st[(i >> 3) * 33 + (i & 7) * 4];
        outp[i] = make_float4(src[0], src[1], src[2], src[3]);
    }
}

// Dual GEMM for heads: mu = bmu + dis*(t@Wmu), lv = blv + dis*(t@Wlv).
__global__ __launch_bounds__(256) void k_gemm2(
    const float* __restrict__ t,
    const float* __restrict__ Wa, const float* __restrict__ Wb,
    const float* __restrict__ ba, const float* __restrict__ bb,
    float* __restrict__ oa, float* __restrict__ ob, int n)
{
    __shared__ float sWa[1024];
    __shared__ float sWb[1024];
    __shared__ float st[256 * 33];
    int tid = threadIdx.x;
    ((float4*)sWa)[tid] = ((const float4*)Wa)[tid];
    ((float4*)sWb)[tid] = ((const float4*)Wb)[tid];

    int base = blockIdx.x * 256;
    int rows = n - base; if (rows > 256) rows = 256;

    const float4* tin = (const float4*)(t + (size_t)base * 32);
    for (int i = tid; i < rows * 8; i += 256) {
        float4 v = tin[i];
        float* dst = &st[(i >> 3) * 33 + (i & 7) * 4];
        dst[0] = v.x; dst[1] = v.y; dst[2] = v.z; dst[3] = v.w;
    }
    __syncthreads();

    float xk[32];
    float4 acca[8], accb[8];
    float dis = 0.0f;
    if (tid < rows) {
#pragma unroll
        for (int j = 0; j < 32; j++) xk[j] = st[tid * 33 + j];
#pragma unroll
        for (int j = 0; j < 8; j++) {
            acca[j] = make_float4(0.f, 0.f, 0.f, 0.f);
            accb[j] = make_float4(0.f, 0.f, 0.f, 0.f);
        }
#pragma unroll
        for (int k = 0; k < 32; k++) {
            float a = xk[k];
#pragma unroll
            for (int j = 0; j < 8; j++) {
                float4 wa = ((const float4*)sWa)[k * 8 + j];
                float4 wb = ((const float4*)sWb)[k * 8 + j];
                acca[j].x += a * wa.x; acca[j].y += a * wa.y;
                acca[j].z += a * wa.z; acca[j].w += a * wa.w;
                accb[j].x += a * wb.x; accb[j].y += a * wb.y;
                accb[j].z += a * wb.z; accb[j].w += a * wb.w;
            }
        }
        dis = g_dis[base + tid];
    }

    // stage + write mu
    __syncthreads();
    if (tid < rows) {
#pragma unroll
        for (int j = 0; j < 8; j++) {
            float4 bv = ((const float4*)ba)[j];
            float* dst = &st[tid * 33 + j * 4];
            dst[0] = bv.x + dis * acca[j].x;
            dst[1] = bv.y + dis * acca[j].y;
            dst[2] = bv.z + dis * acca[j].z;
            dst[3] = bv.w + dis * acca[j].w;
        }
    }
    __syncthreads();
    float4* oap = (float4*)(oa + (size_t)base * 32);
    for (int i = tid; i < rows * 8; i += 256) {
        const float* src = &st[(i >> 3) * 33 + (i & 7) * 4];
        oap[i] = make_float4(src[0], src[1], src[2], src[3]);
    }

    // stage + write lv
    __syncthreads();
    if (tid < rows) {
#pragma unroll
        for (int j = 0; j < 8; j++) {
            float4 bv = ((const float4*)bb)[j];
            float* dst = &st[tid * 33 + j * 4];
            dst[0] = bv.x + dis * accb[j].x;
            dst[1] = bv.y + dis * accb[j].y;
            dst[2] = bv.z + dis * accb[j].z;
            dst[3] = bv.w + dis * accb[j].w;
        }
    }
    __syncthreads();
    float4* obp = (float4*)(ob + (size_t)base * 32);
    for (int i = tid; i < rows * 8; i += 256) {
        const float* src = &st[(i >> 3) * 33 + (i & 7) * 4];
        obp[i] = make_float4(src[0], src[1], src[2], src[3]);
    }
}

// ---------------------------------------------------------------------------
// Launch
// ---------------------------------------------------------------------------

static inline int cdiv(long long a, int b) { return (int)((a + b - 1) / b); }

extern "C" void kernel_launch(void* const* d_in, const int* in_sizes, int n_in,
                              void* d_out, int out_size)
{
    const float* x   = (const float*)d_in[0];
    const void*  ei  = d_in[1];
    const float* W1  = (const float*)d_in[2];
    const float* b1  = (const float*)d_in[3];
    const float* W2  = (const float*)d_in[4];
    const float* b2  = (const float*)d_in[5];
    const float* Wmu = (const float*)d_in[6];
    const float* bmu = (const float*)d_in[7];
    const float* Wlv = (const float*)d_in[8];
    const float* blv = (const float*)d_in[9];

    int N = in_sizes[0] / 32;
    int E = in_sizes[1] / 2;

    float* mu = (float*)d_out;
    float* lv = mu + (size_t)N * 32;

    float* bufA; float* bufB;
    cudaGetSymbolAddress((void**)&bufA, g_bufA);
    cudaGetSymbolAddress((void**)&bufB, g_bufB);

    const int T = 256;
    int gN  = cdiv(N, T);                  // per-node
    int gE4 = cdiv(E, T * 4);              // 4 edges per thread
    int gW  = cdiv((long long)N * 32, T);  // warp-per-node
    int gB  = cdiv(N, 256);                // 256-row GEMM tiles

    // CSR build + layer-1 pre-scale
    k_init<<<gN, T>>>((const int*)ei, E, N);
    k_count<<<gE4, T>>>(ei, E);
    k_rowalloc<<<gW, T>>>(x, bufA, N);     // u1 = dis (.) x
    k_permute<<<gE4, T>>>(ei, E);

    // Layer 1: t1 = A u1; u2 = dis (.) (t1 @ W1 + b1)
    k_agg<0><<<gW, T>>>(bufA, bufB, N);
    k_gemm<<<gB, T>>>(bufB, W1, b1, bufA, N, 1);
    // Layer 2: t2 = A r(u2); u3 = dis (.) (t2 @ W2 + b2)
    k_agg<1><<<gW, T>>>(bufA, bufB, N);
    k_gemm<<<gB, T>>>(bufB, W2, b2, bufA, N, 1);
    // Heads: t3 = A r(u3); mu = t3@Wmu*dis + bmu; lv = t3@Wlv*dis + blv
    k_agg<1><<<gW, T>>>(bufA, bufB, N);
    k_gemm2<<<gB, T>>>(bufB, Wmu, Wlv, bmu, blv, mu, lv, N);
}

// round 9
// speedup vs baseline: 1.0063x; 1.0063x over previous
#include <cuda_runtime.h>
#include <cuda_bf16.h>

// VGAE encoder, pull-based, rank-1 norm factored out, fully fused layers:
//   norm_ij = dis_i*dis_j => A_hat h = dis (.) t,  t_i = u_i + sum_{j in N(i)} u_j,
//   u = dis (.) h (activations stored pre-scaled; relu commutes since dis>0).
// CSR payload is src-only; rows padded to x4 with self-index (compensated in
// the accumulator init), so the gather loop is a clean int4 loop.
// Layer kernel: HALF-WARP per node (lane = float2 channel pair), fused
// shuffle-GEMV epilogue serving 2 nodes per warp.

#define N_MAX 131072
#define E_MAX 2097152   // >= E + 3*N (per-node padding to 4)

// Scratch (device globals; no allocations allowed)
__device__ int   g_is64;
__device__ int   g_alloc;            // CSR region allocator
__device__ int   g_cnt[N_MAX];       // in-degree (excluding self-loop)
__device__ int2  g_row[N_MAX];       // (rowstart, cnt) packed
__device__ int   g_cur[N_MAX];       // permutation cursor
__device__ int   g_adjs[E_MAX];      // CSR payload: src only (padded with self)
__device__ float g_bufA[(size_t)N_MAX * 32];
__device__ float g_bufB[(size_t)N_MAX * 32];

// ---------------------------------------------------------------------------
// Init: zero g_cnt (all blocks); block 0 also detects edge dtype.
// int64 indices (< N ~ 1e5) have all-zero odd int32 words; int32 data never
// has 256 consecutive zero odd words.
// ---------------------------------------------------------------------------

__global__ __launch_bounds__(256) void k_init(const int* __restrict__ ei32,
                                              int E, int n) {
    int i = blockIdx.x * blockDim.x + threadIdx.x;
    if (i < n) g_cnt[i] = 0;
    if (blockIdx.x == 0) {
        int t = threadIdx.x;
        int n_check = 256 < E ? 256 : E;
        int nz = (t < n_check && ei32[2 * t + 1] != 0) ? 1 : 0;
        int any = __syncthreads_or(nz);
        if (t == 0) {
            g_is64 = !any;
            g_alloc = 0;
        }
    }
}

// Count in-degrees, 4 edges per thread (vectorized loads).
__global__ __launch_bounds__(256) void k_count(const void* __restrict__ eiv, int E) {
    int t = blockIdx.x * blockDim.x + threadIdx.x;
    int e0 = t * 4;
    if (e0 >= E) return;
    int d[4];
    int m = (E - e0 < 4) ? (E - e0) : 4;
    if (g_is64) {
        const long long* ei = (const long long*)eiv + (size_t)E + e0;
        if (m == 4) {
            longlong2 a = ((const longlong2*)ei)[0];
            longlong2 b = ((const longlong2*)ei)[1];
            d[0] = (int)a.x; d[1] = (int)a.y; d[2] = (int)b.x; d[3] = (int)b.y;
        } else {
            for (int k = 0; k < m; k++) d[k] = (int)ei[k];
        }
    } else {
        const int* ei = (const int*)eiv + (size_t)E + e0;
        if (m == 4) {
            int4 a = *(const int4*)ei;
            d[0] = a.x; d[1] = a.y; d[2] = a.z; d[3] = a.w;
        } else {
            for (int k = 0; k < m; k++) d[k] = ei[k];
        }
    }
    for (int k = 0; k < m; k++) atomicAdd(&g_cnt[d[k]], 1);
}

// Warp-per-node: CSR region alloc (padded to 4), pad slots filled with the
// node's own index, g_row packed, and u1 = dis (.) x.
__global__ __launch_bounds__(256) void k_rowalloc(const float* __restrict__ x,
                                                  float* __restrict__ u, int n) {
    int warp = (blockIdx.x * blockDim.x + threadIdx.x) >> 5;
    int lane = threadIdx.x & 31;
    if (warp >= n) return;
    int c = 0, rs = 0;
    if (lane == 0) {
        c = g_cnt[warp];
        rs = atomicAdd(&g_alloc, (c + 3) & ~3);
        g_row[warp] = make_int2(rs, c);
        g_cur[warp] = rs;
    }
    c  = __shfl_sync(0xFFFFFFFFu, c, 0);
    rs = __shfl_sync(0xFFFFFFFFu, rs, 0);
    int pad = ((c + 3) & ~3) - c;
    if (lane < pad) g_adjs[rs + c + lane] = warp;  // self-index padding
    float dis = rsqrtf((float)(c + 1));  // +1 self-loop
    int idx = warp * 32 + lane;
    u[idx] = dis * x[idx];
}

// Permute edges into CSR, 4 edges per thread (4 atomics in flight).
__global__ __launch_bounds__(256) void k_permute(const void* __restrict__ eiv, int E) {
    int t = blockIdx.x * blockDim.x + threadIdx.x;
    int e0 = t * 4;
    if (e0 >= E) return;
    int s[4], d[4];
    int m = (E - e0 < 4) ? (E - e0) : 4;
    if (g_is64) {
        const long long* es = (const long long*)eiv + e0;
        const long long* ed = (const long long*)eiv + (size_t)E + e0;
        if (m == 4) {
            longlong2 a = ((const longlong2*)es)[0];
            longlong2 b = ((const longlong2*)es)[1];
            s[0] = (int)a.x; s[1] = (int)a.y; s[2] = (int)b.x; s[3] = (int)b.y;
            longlong2 c = ((const longlong2*)ed)[0];
            longlong2 e = ((const longlong2*)ed)[1];
            d[0] = (int)c.x; d[1] = (int)c.y; d[2] = (int)e.x; d[3] = (int)e.y;
        } else {
            for (int k = 0; k < m; k++) { s[k] = (int)es[k]; d[k] = (int)ed[k]; }
        }
    } else {
        const int* es = (const int*)eiv + e0;
        const int* ed = (const int*)eiv + (size_t)E + e0;
        if (m == 4) {
            int4 a = *(const int4*)es;
            s[0] = a.x; s[1] = a.y; s[2] = a.z; s[3] = a.w;
            int4 c = *(const int4*)ed;
            d[0] = c.x; d[1] = c.y; d[2] = c.z; d[3] = c.w;
        } else {
            for (int k = 0; k < m; k++) { s[k] = es[k]; d[k] = ed[k]; }
        }
    }
    int pos[4];
    for (int k = 0; k < m; k++) pos[k] = atomicAdd(&g_cur[d[k]], 1);
    for (int k = 0; k < m; k++) g_adjs[pos[k]] = s[k];
}

// ---------------------------------------------------------------------------
// Fused layer: HALF-WARP per node. lane: half = lane>>4, sub = lane&15;
// lane holds channels (2sub, 2sub+1) as float2 of node = warp*2 + half.
//   t = (1-pad)*r(u_i) + sum over padded CSR row of r(u_src)   (pad slots = self)
//   o = b + dis*(t @ W);  out = PRE_OUT ? dis*o : o
// ---------------------------------------------------------------------------

__device__ __forceinline__ float2 relu2(float2 v) {
    v.x = fmaxf(v.x, 0.0f); v.y = fmaxf(v.y, 0.0f); return v;
}

template <int RELU, int PRE_OUT>
__global__ __launch_bounds__(256) void k_layer(
    const float* __restrict__ u, const float* __restrict__ W,
    const float* __restrict__ b, float* __restrict__ out, int n)
{
    __shared__ float2 sW2[512];  // W[k][2s..2s+1] at sW2[k*16+s]
    ((float4*)sW2)[threadIdx.x] = ((const float4*)W)[threadIdx.x];
    __syncthreads();

    int gwarp = (blockIdx.x * blockDim.x + threadIdx.x) >> 5;
    int lane = threadIdx.x & 31;
    int half = lane >> 4;
    int sub  = lane & 15;
    int node = gwarp * 2 + half;
    if (node >= n) return;

    const float2* u2 = (const float2*)u;

    int2 rc = g_row[node];
    int rs = rc.x, cnt = rc.y;
    int pc = (cnt + 3) & ~3;
    float dis = rsqrtf((float)(cnt + 1));

    // self term, compensated for self-index padding
    float2 sv = u2[node * 16 + sub];
    if (RELU) sv = relu2(sv);
    float comp = (float)(1 - (pc - cnt));
    float2 acc;
    acc.x = comp * sv.x;
    acc.y = comp * sv.y;

    // clean multiple-of-4 gather loop (int4 adj chunks, broadcast per half-warp)
    for (int j = rs; j < rs + pc; j += 4) {
        int4 e = *(const int4*)(g_adjs + j);
        float2 v0 = u2[e.x * 16 + sub];
        float2 v1 = u2[e.y * 16 + sub];
        float2 v2 = u2[e.z * 16 + sub];
        float2 v3 = u2[e.w * 16 + sub];
        if (RELU) { v0 = relu2(v0); v1 = relu2(v1); v2 = relu2(v2); v3 = relu2(v3); }
        acc.x += (v0.x + v1.x) + (v2.x + v3.x);
        acc.y += (v0.y + v1.y) + (v2.y + v3.y);
    }

    // GEMV within the half-warp: o[2sub,2sub+1] = b + dis * sum_k t[k] W[k][..]
    unsigned hm = 0xFFFFu << (half * 16);
    float sx = 0.0f, sy = 0.0f;
#pragma unroll
    for (int m = 0; m < 16; m++) {
        float t0 = __shfl_sync(hm, acc.x, m, 16);
        float t1 = __shfl_sync(hm, acc.y, m, 16);
        float2 w0 = sW2[(2 * m) * 16 + sub];
        float2 w1 = sW2[(2 * m + 1) * 16 + sub];
        sx += t0 * w0.x + t1 * w1.x;
        sy += t0 * w0.y + t1 * w1.y;
    }
    float2 bv = ((const float2*)b)[sub];
    float sb = PRE_OUT ? dis : 1.0f;
    float ss = PRE_OUT ? dis * dis : dis;
    float2 o;
    o.x = sb * bv.x + ss * sx;
    o.y = sb * bv.y + ss * sy;
    ((float2*)out)[node * 16 + sub] = o;
}

// Fused dual head: one aggregation, two GEMVs (mu and logvar), unscaled outputs.
__global__ __launch_bounds__(256) void k_layer2(
    const float* __restrict__ u,
    const float* __restrict__ Wa, const float* __restrict__ Wb,
    const float* __restrict__ ba, const float* __restrict__ bb,
    float* __restrict__ oa, float* __restrict__ ob, int n)
{
    __shared__ float2 sWa2[512];
    __shared__ float2 sWb2[512];
    ((float4*)sWa2)[threadIdx.x] = ((const float4*)Wa)[threadIdx.x];
    ((float4*)sWb2)[threadIdx.x] = ((const float4*)Wb)[threadIdx.x];
    __syncthreads();

    int gwarp = (blockIdx.x * blockDim.x + threadIdx.x) >> 5;
    int lane = threadIdx.x & 31;
    int half = lane >> 4;
    int sub  = lane & 15;
    int node = gwarp * 2 + half;
    if (node >= n) return;

    const float2* u2 = (const float2*)u;

    int2 rc = g_row[node];
    int rs = rc.x, cnt = rc.y;
    int pc = (cnt + 3) & ~3;
    float dis = rsqrtf((float)(cnt + 1));

    float2 sv = relu2(u2[node * 16 + sub]);
    float comp = (float)(1 - (pc - cnt));
    float2 acc;
    acc.x = comp * sv.x;
    acc.y = comp * sv.y;

    for (int j = rs; j < rs + pc; j += 4) {
        int4 e = *(const int4*)(g_adjs + j);
        float2 v0 = relu2(u2[e.x * 16 + sub]);
        float2 v1 = relu2(u2[e.y * 16 + sub]);
        float2 v2 = relu2(u2[e.z * 16 + sub]);
        float2 v3 = relu2(u2[e.w * 16 + sub]);
        acc.x += (v0.x + v1.x) + (v2.x + v3.x);
        acc.y += (v0.y + v1.y) + (v2.y + v3.y);
    }

    unsigned hm = 0xFFFFu << (half * 16);
    float ax = 0.0f, ay = 0.0f, bx = 0.0f, by = 0.0f;
#pragma unroll
    for (int m = 0; m < 16; m++) {
        float t0 = __shfl_sync(hm, acc.x, m, 16);
        float t1 = __shfl_sync(hm, acc.y, m, 16);
        float2 wa0 = sWa2[(2 * m) * 16 + sub];
        float2 wa1 = sWa2[(2 * m + 1) * 16 + sub];
        float2 wb0 = sWb2[(2 * m) * 16 + sub];
        float2 wb1 = sWb2[(2 * m + 1) * 16 + sub];
        ax += t0 * wa0.x + t1 * wa1.x;
        ay += t0 * wa0.y + t1 * wa1.y;
        bx += t0 * wb0.x + t1 * wb1.x;
        by += t0 * wb0.y + t1 * wb1.y;
    }
    float2 bav = ((const float2*)ba)[sub];
    float2 bbv = ((const float2*)bb)[sub];
    float2 om, ol;
    om.x = bav.x + dis * ax; om.y = bav.y + dis * ay;
    ol.x = bbv.x + dis * bx; ol.y = bbv.y + dis * by;
    ((float2*)oa)[node * 16 + sub] = om;
    ((float2*)ob)[node * 16 + sub] = ol;
}

// ---------------------------------------------------------------------------
// Launch
// ---------------------------------------------------------------------------

static inline int cdiv(long long a, int b) { return (int)((a + b - 1) / b); }

extern "C" void kernel_launch(void* const* d_in, const int* in_sizes, int n_in,
                              void* d_out, int out_size)
{
    const float* x   = (const float*)d_in[0];
    const void*  ei  = d_in[1];
    const float* W1  = (const float*)d_in[2];
    const float* b1  = (const float*)d_in[3];
    const float* W2  = (const float*)d_in[4];
    const float* b2  = (const float*)d_in[5];
    const float* Wmu = (const float*)d_in[6];
    const float* bmu = (const float*)d_in[7];
    const float* Wlv = (const float*)d_in[8];
    const float* blv = (const float*)d_in[9];

    int N = in_sizes[0] / 32;
    int E = in_sizes[1] / 2;

    float* mu = (float*)d_out;
    float* lv = mu + (size_t)N * 32;

    float* bufA; float* bufB;
    cudaGetSymbolAddress((void**)&bufA, g_bufA);
    cudaGetSymbolAddress((void**)&bufB, g_bufB);

    const int T = 256;
    int gN  = cdiv(N, T);                  // per-node
    int gE4 = cdiv(E, T * 4);              // 4 edges per thread
    int gW  = cdiv((long long)N * 32, T);  // warp-per-node (rowalloc)
    int gH  = cdiv((long long)N * 16, T);  // half-warp-per-node (layers)

    // CSR build + layer-1 pre-scale
    k_init<<<gN, T>>>((const int*)ei, E, N);
    k_count<<<gE4, T>>>(ei, E);
    k_rowalloc<<<gW, T>>>(x, bufA, N);     // u1 = dis (.) x, rows padded w/ self
    k_permute<<<gE4, T>>>(ei, E);

    // Layer 1: u2 = dis (.) ((A u1) @ W1 + b1)
    k_layer<0, 1><<<gH, T>>>(bufA, W1, b1, bufB, N);
    // Layer 2: u3 = dis (.) ((A r(u2)) @ W2 + b2)
    k_layer<1, 1><<<gH, T>>>(bufB, W2, b2, bufA, N);
    // Heads: t = A r(u3); mu = dis*(t@Wmu) + bmu; lv = dis*(t@Wlv) + blv
    k_layer2<<<gH, T>>>(bufA, Wmu, Wlv, bmu, blv, mu, lv, N);
}